// round 5
// baseline (speedup 1.0000x reference)
#include <cuda_runtime.h>

// BKT_RNN: B=8192, T=2048, H=4, X=1.
// R5: 2 lanes per row (lane q owns units 2q,2q+1 packed f32x2), 16 rows/warp.
// All dot products via fma.rn.f32x2 (packed, IEEE per half). Closed-form BKT
// latent update (R4). 512 one-warp blocks.

#define TT 2048
#define BB 8192

typedef unsigned long long u64;

__device__ double g_loss_acc;

__global__ void k_zero() { g_loss_acc = 0.0; }

__device__ __forceinline__ float ex2f(float v) {
    float r; asm("ex2.approx.f32 %0, %1;" : "=f"(r) : "f"(v)); return r;
}
__device__ __forceinline__ float rcpf(float v) {
    float r; asm("rcp.approx.f32 %0, %1;" : "=f"(r) : "f"(v)); return r;
}
__device__ __forceinline__ float lg2f(float v) {
    float r; asm("lg2.approx.f32 %0, %1;" : "=f"(r) : "f"(v)); return r;
}
__device__ __forceinline__ u64 pack2(float lo, float hi) {
    u64 r; asm("mov.b64 %0, {%1, %2};" : "=l"(r) : "f"(lo), "f"(hi)); return r;
}
__device__ __forceinline__ void unpack2(u64 v, float& lo, float& hi) {
    asm("mov.b64 {%0, %1}, %2;" : "=f"(lo), "=f"(hi) : "l"(v));
}
__device__ __forceinline__ u64 fma2(u64 a, u64 b, u64 c) {
    u64 d; asm("fma.rn.f32x2 %0, %1, %2, %3;" : "=l"(d) : "l"(a), "l"(b), "l"(c));
    return d;
}

__global__ void __launch_bounds__(32) k_bkt(
    const float* __restrict__ x,   const float* __restrict__ y,
    const float* __restrict__ Wxh, const float* __restrict__ Whh,
    const float* __restrict__ bh,  const float* __restrict__ Wy,
    const float* __restrict__ by,  const float* __restrict__ prior,
    float* __restrict__ corrects,  float* __restrict__ latents)
{
    const unsigned FULL = 0xffffffffu;
    const int lane = threadIdx.x;
    const int q    = lane & 1;                    // half index within row
    const int b    = blockIdx.x * 16 + (lane >> 1);

    // Lane q owns output units (o0,o1)=(2q,2q+1). Input-unit order for the
    // dot products is arranged as (own pair first, other pair second) so no
    // runtime remap is needed after the h exchange.
    const int o0 = 2 * q,     o1 = 2 * q + 1;
    const int t0 = 2 - 2 * q, t1 = 3 - 2 * q;

    // Pre-scale by -log2(e): sigmoid(z) = rcp(1 + ex2(z_scaled)).
    const float NL2E = -1.4426950408889634f;
    // A_i = [Wy[i][o0], Wy[i][o1]] ; W_i = [Whh[i][o0], Whh[i][o1]]
    const u64 A_a = pack2(NL2E * __ldg(Wy + o0 * 4 + o0), NL2E * __ldg(Wy + o0 * 4 + o1));
    const u64 A_b = pack2(NL2E * __ldg(Wy + o1 * 4 + o0), NL2E * __ldg(Wy + o1 * 4 + o1));
    const u64 A_c = pack2(NL2E * __ldg(Wy + t0 * 4 + o0), NL2E * __ldg(Wy + t0 * 4 + o1));
    const u64 A_d = pack2(NL2E * __ldg(Wy + t1 * 4 + o0), NL2E * __ldg(Wy + t1 * 4 + o1));
    const u64 W_a = pack2(NL2E * __ldg(Whh + o0 * 4 + o0), NL2E * __ldg(Whh + o0 * 4 + o1));
    const u64 W_b = pack2(NL2E * __ldg(Whh + o1 * 4 + o0), NL2E * __ldg(Whh + o1 * 4 + o1));
    const u64 W_c = pack2(NL2E * __ldg(Whh + t0 * 4 + o0), NL2E * __ldg(Whh + t0 * 4 + o1));
    const u64 W_d = pack2(NL2E * __ldg(Whh + t1 * 4 + o0), NL2E * __ldg(Whh + t1 * 4 + o1));
    const u64 wx_p = pack2(NL2E * __ldg(Wxh + o0), NL2E * __ldg(Wxh + o1));
    const u64 by_p = pack2(NL2E * __ldg(by + o0),  NL2E * __ldg(by + o1));
    const u64 bh_p = pack2(NL2E * __ldg(bh + o0),  NL2E * __ldg(bh + o1));

    float ha = 0.f, hb = 0.f;     // own hidden units (o0, o1)
    float lat  = __ldg(prior);    // replicated across the lane pair
    float lsum = 0.f;

    const float4* xp = (const float4*)(x + (size_t)b * TT);
    const float4* yp = (const float4*)(y + (size_t)b * TT);
    float4* cp = (float4*)(corrects + (size_t)b * TT);
    float4* lp = (float4*)(latents  + (size_t)b * TT);

    // Prime pipeline (chunk 0 = 8 timesteps). Lane pair shares addresses ->
    // broadcast; 16 distinct 16B segments per warp = coalesced.
    float4 xa = __ldcs(xp + 0), xb = __ldcs(xp + 1);
    float4 ya = __ldcs(yp + 0), yb = __ldcs(yp + 1);

    const int NCHUNK = TT / 8;
    for (int c = 0; c < NCHUNK; ++c) {
        float xv[8] = {xa.x, xa.y, xa.z, xa.w, xb.x, xb.y, xb.z, xb.w};
        float yv[8] = {ya.x, ya.y, ya.z, ya.w, yb.x, yb.y, yb.z, yb.w};

        if (c + 1 < NCHUNK) {   // prefetch next chunk under compute
            xa = __ldcs(xp + 2 * c + 2); xb = __ldcs(xp + 2 * c + 3);
            ya = __ldcs(yp + 2 * c + 2); yb = __ldcs(yp + 2 * c + 3);
        }

        float cb[8], lb[8];
        float prod = 1.f;

        #pragma unroll
        for (int k = 0; k < 8; k++) {
            // Exchange h with partner lane (1x 64-bit bfly).
            const u64 hown = pack2(ha, hb);
            const u64 hoth = __shfl_xor_sync(FULL, hown, 1);
            float hc, hd; unpack2(hoth, hc, hd);

            // Broadcast pairs for packed FMAs.
            const u64 HA = pack2(ha, ha), HB = pack2(hb, hb);
            const u64 HC = pack2(hc, hc), HD = pack2(hd, hd);

            // z_p (2 outputs) and z_h (2 outputs), packed dots.
            u64 zp = by_p;
            zp = fma2(HA, A_a, zp); zp = fma2(HB, A_b, zp);
            zp = fma2(HC, A_c, zp); zp = fma2(HD, A_d, zp);

            const u64 XX = pack2(xv[k], xv[k]);
            u64 zh = fma2(XX, wx_p, bh_p);
            zh = fma2(HA, W_a, zh); zh = fma2(HB, W_b, zh);
            zh = fma2(HC, W_c, zh); zh = fma2(HD, W_d, zh);

            // Sigmoids (scalar MUFU).
            float zp0, zp1; unpack2(zp, zp0, zp1);
            const float p0 = rcpf(1.f + ex2f(zp0));
            const float p1 = rcpf(1.f + ex2f(zp1));
            float zh0, zh1; unpack2(zh, zh0, zh1);
            ha = rcpf(1.f + ex2f(zh0));
            hb = rcpf(1.f + ex2f(zh1));

            // Distribute p: lane0 of pair holds (l,f), lane1 holds (g,s).
            const u64 pp  = pack2(p0, p1);
            const u64 plf = __shfl_sync(FULL, pp, 0, 2);
            const u64 pgs = __shfl_sync(FULL, pp, 1, 2);
            float l_, f_, g_, s_;
            unpack2(plf, l_, f_);
            unpack2(pgs, g_, s_);

            // Closed-form BKT update (exact): m_t == latent.
            const float correct = fmaf(lat, 1.f - s_ - g_, g_);
            lat                 = fmaf(lat, 1.f - f_ - l_, l_);

            // Loss: y in {0,1} -> single factor; lg2 every 4 steps.
            const float cc  = fminf(fmaxf(correct, 1e-7f), 1.0f - 1e-7f);
            const float sel = (yv[k] != 0.f) ? cc : (1.f - cc);
            prod *= sel;
            if ((k & 3) == 3) { lsum += lg2f(prod); prod = 1.f; }

            cb[k] = correct;
            lb[k] = lat;
        }

        // Lane q stores float4 #(2c+q) of this row's chunk.
        const float4 cv = q ? make_float4(cb[4], cb[5], cb[6], cb[7])
                            : make_float4(cb[0], cb[1], cb[2], cb[3]);
        const float4 lv = q ? make_float4(lb[4], lb[5], lb[6], lb[7])
                            : make_float4(lb[0], lb[1], lb[2], lb[3]);
        __stcs(cp + 2 * c + q, cv);
        __stcs(lp + 2 * c + q, lv);
    }

    // Warp reduce (each row counted 2x) + one double atomic per warp.
    #pragma unroll
    for (int o = 16; o > 0; o >>= 1)
        lsum += __shfl_xor_sync(FULL, lsum, o);
    if (lane == 0)
        atomicAdd(&g_loss_acc, (double)lsum);
}

__global__ void k_final(float* __restrict__ loss) {
    // Each row accumulated twice (once per lane of its pair).
    loss[0] = (float)(-0.6931471805599453 * g_loss_acc /
                      (2.0 * (double)BB * (double)TT));
}

extern "C" void kernel_launch(void* const* d_in, const int* in_sizes, int n_in,
                              void* d_out, int out_size) {
    const float* x     = (const float*)d_in[0];
    const float* y     = (const float*)d_in[1];
    const float* Wxh   = (const float*)d_in[2];
    const float* Whh   = (const float*)d_in[3];
    const float* bh    = (const float*)d_in[4];
    const float* Wy    = (const float*)d_in[5];
    const float* by    = (const float*)d_in[6];
    const float* prior = (const float*)d_in[7];

    float* corrects = (float*)d_out;
    float* latents  = (float*)d_out + (size_t)BB * TT;
    float* loss     = (float*)d_out + 2 * (size_t)BB * TT;

    k_zero<<<1, 1>>>();
    k_bkt<<<BB / 16, 32>>>(x, y, Wxh, Whh, bh, Wy, by, prior, corrects, latents);
    k_final<<<1, 1>>>(loss);
}